// round 9
// baseline (speedup 1.0000x reference)
#include <cuda_runtime.h>
#include <math_constants.h>
#include <float.h>

// SMPL nearest-neighbor skinning — Morton-sorted verts+points, warp-collective
// 2-level bounding-sphere traversal (tests amortized across the warp via
// ballot-compacted worklists), exact d2 for every visited vertex.
//
// Exactness: visited verts use the bit-identical reference rounding
//   (dot = fma chain; d2 = add(fma(-2,dot,sx), sv); sv,sx mul/add).
// Winner = lexicographic min (d2, original_index) == jnp.argmin first-index,
// independent of visit order. A sphere is skipped only if
//   dist(warp_bbox, center) > max_lane(s_best) + rad,
//   s_best = sqrt(best + 1e-4)*1.0001,
// so every contained vert's computed d2 strictly exceeds every lane's best.
//
// Output layout: [0,3n) x_bar | [3n,12n) rotation_bar | [12n,28n) T_fwd

static constexpr int   NC     = 16;
static constexpr int   NCELLS = NC * NC * NC;   // 4096
static constexpr float ORG    = -4.0f;
static constexpr float INV_CS = 2.0f;
static constexpr int   MAXN   = 100000;
static constexpr int   MAXVP  = 6896;           // padded (mult of 8)
static constexpr int   NGRP   = MAXVP / 8;      // 862
static constexpr int   NSUP   = (NGRP + 7) / 8; // 108

__device__ int    g_vcount[NCELLS];
__device__ int    g_vstart[NCELLS + 1];
__device__ int    g_vrank[MAXVP];
__device__ int    g_vcellid[MAXVP];
__device__ float4 g_vs[MAXVP];      // sorted verts (x,y,z,|v|^2); pad w=+inf
__device__ int    g_vidx[MAXVP];    // original index; pad INT_MAX

__device__ int    g_pcount[NCELLS];
__device__ int    g_pstart[NCELLS + 1];
__device__ int    g_prank[MAXN];
__device__ int    g_pcellid[MAXN];
__device__ int    g_order[MAXN];

__device__ float4 g_gb[NGRP];       // group bounds (cx,cy,cz,rad)
__device__ float4 g_sb[NSUP];       // super bounds

__device__ __forceinline__ int cell_coord(float x) {
    int c = (int)floorf((x - ORG) * INV_CS);
    return min(NC - 1, max(0, c));
}
__device__ __forceinline__ int spread4(int v) {
    return (v & 1) | ((v & 2) << 2) | ((v & 4) << 4) | ((v & 8) << 6);
}
__device__ __forceinline__ int morton_cell(float x, float y, float z) {
    return spread4(cell_coord(x)) | (spread4(cell_coord(y)) << 1)
         | (spread4(cell_coord(z)) << 2);
}

// ───────────── build ─────────────
__global__ void zero_counts(int nv) {
    int i = blockIdx.x * blockDim.x + threadIdx.x;    // 4096
    if (i < NCELLS) { g_vcount[i] = 0; g_pcount[i] = 0; }
    for (int k = i; k < MAXVP; k += NCELLS) {
        if (k >= nv) {
            g_vs[k]   = make_float4(0.f, 0.f, 0.f, CUDART_INF_F);
            g_vidx[k] = 0x7FFFFFFF;
        }
    }
}

__global__ void count_kernel(const float* __restrict__ verts,
                             const float* __restrict__ xyz, int nv, int n) {
    int i = blockIdx.x * blockDim.x + threadIdx.x;
    if (i < nv) {
        int cid = morton_cell(verts[3 * i], verts[3 * i + 1], verts[3 * i + 2]);
        g_vcellid[i] = cid;
        g_vrank[i] = atomicAdd(&g_vcount[cid], 1);
    }
    if (i < n) {
        int cid = morton_cell(xyz[3 * i], xyz[3 * i + 1], xyz[3 * i + 2]);
        g_pcellid[i] = cid;
        g_prank[i] = atomicAdd(&g_pcount[cid], 1);
    }
}

__global__ void __launch_bounds__(1024) scan_offsets() {
    __shared__ int part[1024];
    const int t = threadIdx.x;
    int* cnt = blockIdx.x ? g_pcount : g_vcount;
    int* st  = blockIdx.x ? g_pstart : g_vstart;
    const int CHUNK = NCELLS / 1024;   // 4
    int base = t * CHUNK, s = 0;
    #pragma unroll
    for (int k = 0; k < CHUNK; ++k) s += cnt[base + k];
    part[t] = s;
    __syncthreads();
    for (int off = 1; off < 1024; off <<= 1) {
        int v = (t >= off) ? part[t - off] : 0;
        __syncthreads(); part[t] += v; __syncthreads();
    }
    int excl = part[t] - s;
    #pragma unroll
    for (int k = 0; k < CHUNK; ++k) { st[base + k] = excl; excl += cnt[base + k]; }
    if (t == 1023) st[NCELLS] = part[1023];
}

__global__ void scatter_kernel(const float* __restrict__ verts, int nv, int n) {
    int i = blockIdx.x * blockDim.x + threadIdx.x;
    if (i < nv) {
        float x = verts[3 * i], y = verts[3 * i + 1], z = verts[3 * i + 2];
        float sv = __fadd_rn(__fadd_rn(__fmul_rn(x, x), __fmul_rn(y, y)),
                             __fmul_rn(z, z));
        int pos = g_vstart[g_vcellid[i]] + g_vrank[i];
        g_vs[pos]   = make_float4(x, y, z, sv);
        g_vidx[pos] = i;
    }
    if (i < n) {
        g_order[g_pstart[g_pcellid[i]] + g_prank[i]] = i;
    }
}

__global__ void group_bounds() {
    int g = blockIdx.x * blockDim.x + threadIdx.x;
    if (g >= NGRP) return;
    float mnx = FLT_MAX, mny = FLT_MAX, mnz = FLT_MAX;
    float mxx = -FLT_MAX, mxy = -FLT_MAX, mxz = -FLT_MAX;
    bool any = false;
    #pragma unroll
    for (int k = 0; k < 8; ++k) {
        float4 v = g_vs[g * 8 + k];
        if (isinf(v.w)) continue;
        any = true;
        mnx = fminf(mnx, v.x); mxx = fmaxf(mxx, v.x);
        mny = fminf(mny, v.y); mxy = fmaxf(mxy, v.y);
        mnz = fminf(mnz, v.z); mxz = fmaxf(mxz, v.z);
    }
    if (!any) { g_gb[g] = make_float4(1e15f, 1e15f, 1e15f, 0.f); return; }
    float cx = 0.5f * (mnx + mxx), cy = 0.5f * (mny + mxy), cz = 0.5f * (mnz + mxz);
    float m2 = 0.f;
    #pragma unroll
    for (int k = 0; k < 8; ++k) {
        float4 v = g_vs[g * 8 + k];
        if (isinf(v.w)) continue;
        float dx = v.x - cx, dy = v.y - cy, dz = v.z - cz;
        m2 = fmaxf(m2, dx * dx + dy * dy + dz * dz);
    }
    g_gb[g] = make_float4(cx, cy, cz, sqrtf(m2) * 1.0001f + 1e-5f);
}

__global__ void super_bounds() {
    int s = blockIdx.x * blockDim.x + threadIdx.x;
    if (s >= NSUP) return;
    float mnx = FLT_MAX, mny = FLT_MAX, mnz = FLT_MAX;
    float mxx = -FLT_MAX, mxy = -FLT_MAX, mxz = -FLT_MAX;
    bool any = false;
    for (int k = 0; k < 8; ++k) {
        int g = s * 8 + k;
        if (g >= NGRP) break;
        float4 b = g_gb[g];
        if (b.x > 1e14f) continue;
        any = true;
        mnx = fminf(mnx, b.x - b.w); mxx = fmaxf(mxx, b.x + b.w);
        mny = fminf(mny, b.y - b.w); mxy = fmaxf(mxy, b.y + b.w);
        mnz = fminf(mnz, b.z - b.w); mxz = fmaxf(mxz, b.z + b.w);
    }
    if (!any) { g_sb[s] = make_float4(1e15f, 1e15f, 1e15f, 0.f); return; }
    float cx = 0.5f * (mnx + mxx), cy = 0.5f * (mny + mxy), cz = 0.5f * (mnz + mxz);
    float mr = 0.f;
    for (int k = 0; k < 8; ++k) {
        int g = s * 8 + k;
        if (g >= NGRP) break;
        float4 b = g_gb[g];
        if (b.x > 1e14f) continue;
        float dx = b.x - cx, dy = b.y - cy, dz = b.z - cz;
        mr = fmaxf(mr, sqrtf(dx * dx + dy * dy + dz * dz) + b.w);
    }
    g_sb[s] = make_float4(cx, cy, cz, mr * 1.0001f + 1e-5f);
}

// ───────────── main kernel ─────────────
__device__ __forceinline__ float wmin(float v) {
    #pragma unroll
    for (int o = 16; o; o >>= 1) v = fminf(v, __shfl_xor_sync(0xFFFFFFFFu, v, o));
    return v;
}
__device__ __forceinline__ float wmax(float v) {
    #pragma unroll
    for (int o = 16; o; o >>= 1) v = fmaxf(v, __shfl_xor_sync(0xFFFFFFFFu, v, o));
    return v;
}

__global__ void __launch_bounds__(256) nn_kernel(
    const float* __restrict__ xyz,
    const float* __restrict__ rot,
    const float* __restrict__ W,
    const float* __restrict__ bones,
    float* __restrict__ out,
    int n, int nv)
{
    __shared__ float4 sSB[NSUP];
    __shared__ float  sB[24 * 16];
    __shared__ unsigned short sGrp[8][NGRP];
    __shared__ unsigned char  sSup[8][NSUP];

    const int tid  = threadIdx.x;
    const int lane = tid & 31;
    const int wid  = tid >> 5;

    for (int j = tid; j < NSUP; j += blockDim.x) sSB[j] = g_sb[j];
    for (int j = tid; j < 24 * 16; j += blockDim.x) sB[j] = bones[j];
    __syncthreads();

    const int i = blockIdx.x * blockDim.x + tid;
    const bool valid = (i < n);
    const int ic  = valid ? i : (n - 1);
    const int pid = g_order[ic];

    const float px = xyz[3 * pid + 0];
    const float py = xyz[3 * pid + 1];
    const float pz = xyz[3 * pid + 2];
    const float sx = __fadd_rn(__fadd_rn(__fmul_rn(px, px), __fmul_rn(py, py)),
                               __fmul_rn(pz, pz));

    float best = CUDART_INF_F;
    int   bidx = 0x7FFFFFFF;

    auto eval_group = [&](int g) {
        #pragma unroll
        for (int k = 0; k < 8; ++k) {
            float4 v = g_vs[g * 8 + k];
            float dot = __fmaf_rn(px, v.x, 0.0f);
            dot = __fmaf_rn(py, v.y, dot);
            dot = __fmaf_rn(pz, v.z, dot);
            float d2 = __fadd_rn(__fmaf_rn(-2.0f, dot, sx), v.w);
            int idx = g_vidx[g * 8 + k];
            bool better = (d2 < best) || (d2 == best && idx < bidx);
            best = better ? d2 : best;
            bidx = better ? idx : bidx;
        }
    };

    // Seed: rank-proportional vert along the shared Morton curve.
    {
        long vr = (long)ic * nv / n;
        int gs = min((int)(vr >> 3), NGRP - 1);
        eval_group(gs);
        if (gs + 1 < NGRP) eval_group(gs + 1);
        if (gs > 0) eval_group(gs - 1);
    }
    float s_best = __fsqrt_rn(best + 1e-4f) * 1.0001f;

    // Warp-collective bound: point bbox + loosest lane radius.
    const float lox = wmin(px), hix = wmax(px);
    const float loy = wmin(py), hiy = wmax(py);
    const float loz = wmin(pz), hiz = wmax(pz);
    const float smax = wmax(s_best);

    // Pass 1: supers, lane-parallel, ballot-compacted.
    int scount = 0;
    #pragma unroll
    for (int base = 0; base < 128; base += 32) {
        int s = base + lane;
        bool pass = false;
        if (s < NSUP) {
            float4 b = sSB[s];
            float dx = fmaxf(0.f, fmaxf(lox - b.x, b.x - hix));
            float dy = fmaxf(0.f, fmaxf(loy - b.y, b.y - hiy));
            float dz = fmaxf(0.f, fmaxf(loz - b.z, b.z - hiz));
            float thr = smax + b.w;
            pass = (dx * dx + dy * dy + dz * dz) <= thr * thr;
        }
        unsigned m = __ballot_sync(0xFFFFFFFFu, pass);
        if (pass) sSup[wid][scount + __popc(m & ((1u << lane) - 1))] = (unsigned char)s;
        scount += __popc(m);
    }

    // Pass 2: groups of passing supers (lanes 0-7 test), compacted.
    int gcount = 0;
    for (int e = 0; e < scount; ++e) {
        int sid = sSup[wid][e];
        int g = sid * 8 + (lane & 7);
        bool pass = false;
        if (lane < 8 && g < NGRP) {
            float4 b = g_gb[g];
            float dx = fmaxf(0.f, fmaxf(lox - b.x, b.x - hix));
            float dy = fmaxf(0.f, fmaxf(loy - b.y, b.y - hiy));
            float dz = fmaxf(0.f, fmaxf(loz - b.z, b.z - hiz));
            float thr = smax + b.w;
            pass = (dx * dx + dy * dy + dz * dz) <= thr * thr;
        }
        unsigned m = __ballot_sync(0xFFFFFFFFu, pass);
        if (pass) sGrp[wid][gcount + __popc(m & ((1u << lane) - 1))] = (unsigned short)g;
        gcount += __popc(m);
    }

    // Pass 3: uniform, branch-free evaluation of the compact group list.
    for (int e = 0; e < gcount; ++e) eval_group(sGrp[wid][e]);

    if (!valid) return;

    // ── skinning epilogue ──
    float T[16];
    #pragma unroll
    for (int k = 0; k < 16; ++k) T[k] = 0.0f;
    const float* wrow = W + (size_t)bidx * 24;
    #pragma unroll
    for (int j = 0; j < 24; ++j) {
        float wj = __ldg(wrow + j);
        #pragma unroll
        for (int k = 0; k < 16; ++k) T[k] = fmaf(wj, sB[j * 16 + k], T[k]);
    }

    #pragma unroll
    for (int ii = 0; ii < 3; ++ii) {
        float v = T[4 * ii + 3];
        v = fmaf(T[4 * ii + 0], px, v);
        v = fmaf(T[4 * ii + 1], py, v);
        v = fmaf(T[4 * ii + 2], pz, v);
        out[3 * pid + ii] = v;
    }

    const float4 q = *reinterpret_cast<const float4*>(rot + 4 * pid);
    float qn = rsqrtf(q.x * q.x + q.y * q.y + q.z * q.z + q.w * q.w);
    float qr = q.x * qn, qx = q.y * qn, qy = q.z * qn, qz = q.w * qn;

    float R[3][3];
    R[0][0] = 1.0f - 2.0f * (qy * qy + qz * qz);
    R[0][1] = 2.0f * (qx * qy - qr * qz);
    R[0][2] = 2.0f * (qx * qz + qr * qy);
    R[1][0] = 2.0f * (qx * qy + qr * qz);
    R[1][1] = 1.0f - 2.0f * (qx * qx + qz * qz);
    R[1][2] = 2.0f * (qy * qz - qr * qx);
    R[2][0] = 2.0f * (qx * qz - qr * qy);
    R[2][1] = 2.0f * (qy * qz + qr * qx);
    R[2][2] = 1.0f - 2.0f * (qx * qx + qy * qy);

    float* out_R = out + (size_t)3 * n;
    #pragma unroll
    for (int ii = 0; ii < 3; ++ii) {
        #pragma unroll
        for (int k = 0; k < 3; ++k) {
            float v = T[4 * ii + 0] * R[0][k];
            v = fmaf(T[4 * ii + 1], R[1][k], v);
            v = fmaf(T[4 * ii + 2], R[2][k], v);
            out_R[9 * pid + 3 * ii + k] = v;
        }
    }

    float4* out_T = reinterpret_cast<float4*>(out + (size_t)12 * n) + (size_t)4 * pid;
    #pragma unroll
    for (int k = 0; k < 4; ++k)
        out_T[k] = make_float4(T[4 * k + 0], T[4 * k + 1], T[4 * k + 2], T[4 * k + 3]);
}

extern "C" void kernel_launch(void* const* d_in, const int* in_sizes, int n_in,
                              void* d_out, int out_size)
{
    const float* xyz   = (const float*)d_in[0];
    const float* rot   = (const float*)d_in[1];
    const float* verts = (const float*)d_in[2];
    const float* W     = (const float*)d_in[3];
    const float* bones = (const float*)d_in[4];
    float* out = (float*)d_out;

    const int n  = in_sizes[0] / 3;   // 100000
    const int nv = in_sizes[2] / 3;   // 6890
    const int mx = (n > nv) ? n : nv;

    zero_counts<<<NCELLS / 256, 256>>>(nv);
    count_kernel<<<(mx + 255) / 256, 256>>>(verts, xyz, nv, n);
    scan_offsets<<<2, 1024>>>();
    scatter_kernel<<<(mx + 255) / 256, 256>>>(verts, nv, n);
    group_bounds<<<(NGRP + 255) / 256, 256>>>();
    super_bounds<<<1, 128>>>();
    nn_kernel<<<(n + 255) / 256, 256>>>(xyz, rot, W, bones, out, n, nv);
}

// round 10
// speedup vs baseline: 1.4452x; 1.4452x over previous
#include <cuda_runtime.h>
#include <math_constants.h>
#include <float.h>

// SMPL NN skinning — one point per WARP collective search.
// Verts Morton-sorted into groups of 8 with bounding spheres (862 groups,
// 108 supers). Per point: lanes test supers -> ub = min(dist+rad) (upper
// bound on NN distance, triangle ineq., fp slack baked in); groups of
// passing supers tested & compacted; candidate verts evaluated with the
// bit-exact reference d2; lex (d2, orig_idx) warp reduction = first-index
// argmin. All control flow warp-uniform; pruning provably conservative.
// Output: [0,3n) x_bar | [3n,12n) rotation_bar | [12n,28n) T_fwd

static constexpr int   NC     = 16;
static constexpr int   NCELLS = NC * NC * NC;    // 4096
static constexpr float ORG    = -4.0f;
static constexpr float INV_CS = 2.0f;
static constexpr int   MAXVP  = 6896;            // mult of 8
static constexpr int   NGRP   = MAXVP / 8;       // 862
static constexpr int   NSUP   = (NGRP + 7) / 8;  // 108

__device__ float4 g_vs[MAXVP];    // sorted verts (x,y,z,|v|^2); pad w=+inf
__device__ int    g_vidx[MAXVP];  // original index; pad INT_MAX
__device__ float4 g_gb[NGRP];     // group spheres (cx,cy,cz,rad); empty cx=1e15
__device__ float4 g_sb[NSUP];     // super spheres

__device__ __forceinline__ int cell_coord(float x) {
    int c = (int)floorf((x - ORG) * INV_CS);
    return min(NC - 1, max(0, c));
}
__device__ __forceinline__ int spread4(int v) {
    return (v & 1) | ((v & 2) << 2) | ((v & 4) << 4) | ((v & 8) << 6);
}
__device__ __forceinline__ int morton_cell(float x, float y, float z) {
    return spread4(cell_coord(x)) | (spread4(cell_coord(y)) << 1)
         | (spread4(cell_coord(z)) << 2);
}

// ─────────── single-CTA build: bin + scan + scatter + bounds ───────────
__global__ void __launch_bounds__(1024) build_kernel(const float* __restrict__ verts,
                                                     int nv)
{
    __shared__ int    scnt[NCELLS];
    __shared__ int    part[1024];
    __shared__ float4 sgb[NGRP];
    const int tid = threadIdx.x;

    for (int i = tid; i < NCELLS; i += 1024) scnt[i] = 0;
    __syncthreads();

    float lx[8], ly[8], lz[8];
    int   lc[8], lr[8];
    int cnt = 0;
    for (int j = tid; j < nv; j += 1024) {
        float x = verts[3 * j], y = verts[3 * j + 1], z = verts[3 * j + 2];
        int cid = morton_cell(x, y, z);
        lx[cnt] = x; ly[cnt] = y; lz[cnt] = z;
        lc[cnt] = cid;
        lr[cnt] = atomicAdd(&scnt[cid], 1);
        ++cnt;
    }
    __syncthreads();

    // exclusive scan of 4096 cell counts (4 per thread + block scan)
    int base = tid * 4;
    int c0 = scnt[base], c1 = scnt[base + 1], c2 = scnt[base + 2], c3 = scnt[base + 3];
    int s = c0 + c1 + c2 + c3;
    part[tid] = s;
    __syncthreads();
    for (int off = 1; off < 1024; off <<= 1) {
        int v = (tid >= off) ? part[tid - off] : 0;
        __syncthreads(); part[tid] += v; __syncthreads();
    }
    int excl = part[tid] - s;
    scnt[base]     = excl;
    scnt[base + 1] = excl + c0;
    scnt[base + 2] = excl + c0 + c1;
    scnt[base + 3] = excl + c0 + c1 + c2;
    __syncthreads();

    // scatter (exact-rounded |v|^2) + pad tail
    for (int u = 0; u < cnt; ++u) {
        int pos = scnt[lc[u]] + lr[u];
        float x = lx[u], y = ly[u], z = lz[u];
        float sv = __fadd_rn(__fadd_rn(__fmul_rn(x, x), __fmul_rn(y, y)),
                             __fmul_rn(z, z));
        g_vs[pos]   = make_float4(x, y, z, sv);
        g_vidx[pos] = tid + 1024 * u;
    }
    for (int j = nv + tid; j < MAXVP; j += 1024) {
        g_vs[j]   = make_float4(0.f, 0.f, 0.f, CUDART_INF_F);
        g_vidx[j] = 0x7FFFFFFF;
    }
    __syncthreads();   // block-scope global visibility

    // group spheres
    for (int g = tid; g < NGRP; g += 1024) {
        float mnx = FLT_MAX, mny = FLT_MAX, mnz = FLT_MAX;
        float mxx = -FLT_MAX, mxy = -FLT_MAX, mxz = -FLT_MAX;
        bool any = false;
        #pragma unroll
        for (int k = 0; k < 8; ++k) {
            float4 v = g_vs[g * 8 + k];
            if (isinf(v.w)) continue;
            any = true;
            mnx = fminf(mnx, v.x); mxx = fmaxf(mxx, v.x);
            mny = fminf(mny, v.y); mxy = fmaxf(mxy, v.y);
            mnz = fminf(mnz, v.z); mxz = fmaxf(mxz, v.z);
        }
        float4 b;
        if (!any) {
            b = make_float4(1e15f, 1e15f, 1e15f, 0.f);
        } else {
            float cx = 0.5f * (mnx + mxx), cy = 0.5f * (mny + mxy), cz = 0.5f * (mnz + mxz);
            float m2 = 0.f;
            #pragma unroll
            for (int k = 0; k < 8; ++k) {
                float4 v = g_vs[g * 8 + k];
                if (isinf(v.w)) continue;
                float dx = v.x - cx, dy = v.y - cy, dz = v.z - cz;
                m2 = fmaxf(m2, dx * dx + dy * dy + dz * dz);
            }
            b = make_float4(cx, cy, cz, sqrtf(m2) * 1.0002f + 1e-5f);
        }
        sgb[g] = b;
        g_gb[g] = b;
    }
    __syncthreads();

    // super spheres
    if (tid < NSUP) {
        float mnx = FLT_MAX, mny = FLT_MAX, mnz = FLT_MAX;
        float mxx = -FLT_MAX, mxy = -FLT_MAX, mxz = -FLT_MAX;
        bool any = false;
        for (int k = 0; k < 8; ++k) {
            int g = tid * 8 + k;
            if (g >= NGRP) break;
            float4 b = sgb[g];
            if (b.x > 1e14f) continue;
            any = true;
            mnx = fminf(mnx, b.x - b.w); mxx = fmaxf(mxx, b.x + b.w);
            mny = fminf(mny, b.y - b.w); mxy = fmaxf(mxy, b.y + b.w);
            mnz = fminf(mnz, b.z - b.w); mxz = fmaxf(mxz, b.z + b.w);
        }
        if (!any) {
            g_sb[tid] = make_float4(1e15f, 1e15f, 1e15f, 0.f);
        } else {
            float cx = 0.5f * (mnx + mxx), cy = 0.5f * (mny + mxy), cz = 0.5f * (mnz + mxz);
            float mr = 0.f;
            for (int k = 0; k < 8; ++k) {
                int g = tid * 8 + k;
                if (g >= NGRP) break;
                float4 b = sgb[g];
                if (b.x > 1e14f) continue;
                float dx = b.x - cx, dy = b.y - cy, dz = b.z - cz;
                mr = fmaxf(mr, sqrtf(dx * dx + dy * dy + dz * dz) + b.w);
            }
            g_sb[tid] = make_float4(cx, cy, cz, mr * 1.0002f + 1e-5f);
        }
    }
}

// ─────────────────────── NN + skinning kernel ───────────────────────
__global__ void __launch_bounds__(256) nn_kernel(
    const float* __restrict__ xyz,
    const float* __restrict__ rot,
    const float* __restrict__ W,
    const float* __restrict__ bones,
    float* __restrict__ out,
    int n)
{
    __shared__ float4 sGB[NGRP];
    __shared__ float4 sSB[NSUP];
    __shared__ float  sB[24 * 16];
    __shared__ unsigned char  supL[8][112];
    __shared__ unsigned short grpL[8][896];

    const int tid = threadIdx.x, lane = tid & 31, w = tid >> 5;
    for (int j = tid; j < NGRP; j += 256) sGB[j] = g_gb[j];
    for (int j = tid; j < NSUP; j += 256) sSB[j] = g_sb[j];
    for (int j = tid; j < 24 * 16; j += 256) sB[j] = bones[j];
    __syncthreads();

    const int warpBase = (blockIdx.x * 8 + w) * 32;
    int myIdx = 0;

    for (int k = 0; k < 32; ++k) {
        const int pt = warpBase + k;
        if (pt >= n) break;                 // warp-uniform

        const float px = xyz[3 * pt + 0];
        const float py = xyz[3 * pt + 1];
        const float pz = xyz[3 * pt + 2];
        const float sx = __fadd_rn(__fadd_rn(__fmul_rn(px, px), __fmul_rn(py, py)),
                                   __fmul_rn(pz, pz));

        // ── super pass: a = safe upper (dist+rad), b = safe lower (dist-rad)
        float ub = CUDART_INF_F;
        float bs[4];
        #pragma unroll
        for (int r = 0; r < 4; ++r) {
            int s = r * 32 + lane;
            float a = CUDART_INF_F, b = CUDART_INF_F;
            if (s < NSUP) {
                float4 sb = sSB[s];
                if (sb.x < 1e14f) {
                    float dx = px - sb.x, dy = py - sb.y, dz = pz - sb.z;
                    float d2 = fmaxf(dx * dx + dy * dy + dz * dz, 1e-20f);
                    float d = d2 * __frsqrt_rn(d2);
                    a = __fmaf_rn(d, 1.0005f,  sb.w + 1e-4f);
                    b = __fmaf_rn(d, 0.9995f, -sb.w - 1e-4f);
                }
            }
            bs[r] = b;
            ub = fminf(ub, a);
        }
        #pragma unroll
        for (int o = 16; o; o >>= 1) ub = fminf(ub, __shfl_xor_sync(0xFFFFFFFFu, ub, o));

        int sc = 0;
        #pragma unroll
        for (int r = 0; r < 4; ++r) {
            bool pass = bs[r] <= ub;
            unsigned m = __ballot_sync(0xFFFFFFFFu, pass);
            if (pass) supL[w][sc + __popc(m & ((1u << lane) - 1))] =
                          (unsigned char)(r * 32 + lane);
            sc += __popc(m);
        }

        // ── group pass over passing supers (4 supers x 8 lanes per chunk)
        int gc = 0;
        float ubg = ub;
        for (int t = 0; t < sc; t += 4) {
            int si = t + (lane >> 3);
            bool vl = (si < sc);
            int g = vl ? (int)supL[w][si] * 8 + (lane & 7) : 0;
            float a = CUDART_INF_F, b = CUDART_INF_F;
            if (vl && g < NGRP) {
                float4 gb = sGB[g];
                if (gb.x < 1e14f) {
                    float dx = px - gb.x, dy = py - gb.y, dz = pz - gb.z;
                    float d2 = fmaxf(dx * dx + dy * dy + dz * dz, 1e-20f);
                    float d = d2 * __frsqrt_rn(d2);
                    a = __fmaf_rn(d, 1.0005f,  gb.w + 1e-4f);
                    b = __fmaf_rn(d, 0.9995f, -gb.w - 1e-4f);
                }
            }
            ubg = fminf(ubg, a);
            bool pass = (b <= ub);
            unsigned m = __ballot_sync(0xFFFFFFFFu, pass);
            if (pass) grpL[w][gc + __popc(m & ((1u << lane) - 1))] = (unsigned short)g;
            gc += __popc(m);
        }
        #pragma unroll
        for (int o = 16; o; o >>= 1) ubg = fminf(ubg, __shfl_xor_sync(0xFFFFFFFFu, ubg, o));

        // ── filter collected groups by tighter ubg (in-place compact)
        int gc2 = 0;
        for (int t = 0; t < gc; t += 32) {
            int sl = t + lane;
            bool vl = (sl < gc);
            int g = vl ? (int)grpL[w][sl] : 0;
            float b = CUDART_INF_F;
            if (vl) {
                float4 gb = sGB[g];
                float dx = px - gb.x, dy = py - gb.y, dz = pz - gb.z;
                float d2 = fmaxf(dx * dx + dy * dy + dz * dz, 1e-20f);
                float d = d2 * __frsqrt_rn(d2);
                b = __fmaf_rn(d, 0.9995f, -gb.w - 1e-4f);
            }
            bool pass = vl && (b <= ubg);
            unsigned m = __ballot_sync(0xFFFFFFFFu, pass);
            if (pass) grpL[w][gc2 + __popc(m & ((1u << lane) - 1))] = (unsigned short)g;
            gc2 += __popc(m);
        }

        // ── exact eval of candidate verts (bit-exact reference d2)
        float bl = CUDART_INF_F;
        int   bi = 0x7FFFFFFF;
        const int total = gc2 * 8;
        for (int t = lane; t < total; t += 32) {
            int g = grpL[w][t >> 3];
            int kk = t & 7;
            float4 v = g_vs[g * 8 + kk];
            int idx = g_vidx[g * 8 + kk];
            float dot = __fmaf_rn(px, v.x, 0.0f);
            dot = __fmaf_rn(py, v.y, dot);
            dot = __fmaf_rn(pz, v.z, dot);
            float d2 = __fadd_rn(__fmaf_rn(-2.0f, dot, sx), v.w);
            bool better = (d2 < bl) || (d2 == bl && idx < bi);
            bl = better ? d2 : bl;
            bi = better ? idx : bi;
        }
        #pragma unroll
        for (int o = 16; o; o >>= 1) {
            float ob = __shfl_xor_sync(0xFFFFFFFFu, bl, o);
            int   oi = __shfl_xor_sync(0xFFFFFFFFu, bi, o);
            bool bet = (ob < bl) || (ob == bl && oi < bi);
            bl = bet ? ob : bl;
            bi = bet ? oi : bi;
        }
        if (lane == k) myIdx = bi;
    }

    // ── per-lane skinning epilogue ──
    const int pt = warpBase + lane;
    if (pt >= n) return;
    const int bidx = myIdx;

    const float px = xyz[3 * pt + 0];
    const float py = xyz[3 * pt + 1];
    const float pz = xyz[3 * pt + 2];

    float T[16];
    #pragma unroll
    for (int k = 0; k < 16; ++k) T[k] = 0.0f;
    const float* wrow = W + (size_t)bidx * 24;
    #pragma unroll
    for (int j = 0; j < 24; ++j) {
        float wj = __ldg(wrow + j);
        #pragma unroll
        for (int k = 0; k < 16; ++k) T[k] = fmaf(wj, sB[j * 16 + k], T[k]);
    }

    #pragma unroll
    for (int ii = 0; ii < 3; ++ii) {
        float v = T[4 * ii + 3];
        v = fmaf(T[4 * ii + 0], px, v);
        v = fmaf(T[4 * ii + 1], py, v);
        v = fmaf(T[4 * ii + 2], pz, v);
        out[3 * pt + ii] = v;
    }

    const float4 q = *reinterpret_cast<const float4*>(rot + 4 * pt);
    float qn = rsqrtf(q.x * q.x + q.y * q.y + q.z * q.z + q.w * q.w);
    float qr = q.x * qn, qx = q.y * qn, qy = q.z * qn, qz = q.w * qn;

    float R[3][3];
    R[0][0] = 1.0f - 2.0f * (qy * qy + qz * qz);
    R[0][1] = 2.0f * (qx * qy - qr * qz);
    R[0][2] = 2.0f * (qx * qz + qr * qy);
    R[1][0] = 2.0f * (qx * qy + qr * qz);
    R[1][1] = 1.0f - 2.0f * (qx * qx + qz * qz);
    R[1][2] = 2.0f * (qy * qz - qr * qx);
    R[2][0] = 2.0f * (qx * qz - qr * qy);
    R[2][1] = 2.0f * (qy * qz + qr * qx);
    R[2][2] = 1.0f - 2.0f * (qx * qx + qy * qy);

    float* out_R = out + (size_t)3 * n;
    #pragma unroll
    for (int ii = 0; ii < 3; ++ii) {
        #pragma unroll
        for (int k = 0; k < 3; ++k) {
            float v = T[4 * ii + 0] * R[0][k];
            v = fmaf(T[4 * ii + 1], R[1][k], v);
            v = fmaf(T[4 * ii + 2], R[2][k], v);
            out_R[9 * pt + 3 * ii + k] = v;
        }
    }

    float4* out_T = reinterpret_cast<float4*>(out + (size_t)12 * n) + (size_t)4 * pt;
    #pragma unroll
    for (int k = 0; k < 4; ++k)
        out_T[k] = make_float4(T[4 * k + 0], T[4 * k + 1], T[4 * k + 2], T[4 * k + 3]);
}

extern "C" void kernel_launch(void* const* d_in, const int* in_sizes, int n_in,
                              void* d_out, int out_size)
{
    const float* xyz   = (const float*)d_in[0];
    const float* rot   = (const float*)d_in[1];
    const float* verts = (const float*)d_in[2];
    const float* W     = (const float*)d_in[3];
    const float* bones = (const float*)d_in[4];
    float* out = (float*)d_out;

    const int n  = in_sizes[0] / 3;   // 100000
    const int nv = in_sizes[2] / 3;   // 6890

    build_kernel<<<1, 1024>>>(verts, nv);
    nn_kernel<<<(n + 255) / 256, 256>>>(xyz, rot, W, bones, out, n);
}

// round 13
// speedup vs baseline: 2.2917x; 1.5857x over previous
#include <cuda_runtime.h>
#include <math_constants.h>
#include <float.h>

// SMPL NN skinning — per-thread 3-pass pruned exact search.
//  A: exact d2 on 432 Morton-subsampled verts -> ub2 (computed candidate d2)
//  B: packed-f32x2 sphere tests (supers then their groups), branch-free
//     slot-trick compaction WITH DUMMY SLOT (fail-stores routed to slot CAP)
//  C: exact bit-identical reference d2 on candidate groups, lex (d2,idx) min
// Skip is provably conservative: skip group iff d_c2 > (r_s+rad)^2 with
// r_s^2=(ub2+1e-3)*1.001 ⇒ every contained vert's computed-exact d2 > best.
// Output: [0,3n) x_bar | [3n,12n) rotation_bar | [12n,28n) T_fwd

typedef unsigned long long ull;

__device__ __forceinline__ ull f2_mul(ull a, ull b) {
    ull r; asm("mul.rn.f32x2 %0,%1,%2;" : "=l"(r) : "l"(a), "l"(b)); return r;
}
__device__ __forceinline__ ull f2_fma(ull a, ull b, ull c) {
    ull r; asm("fma.rn.f32x2 %0,%1,%2,%3;" : "=l"(r) : "l"(a), "l"(b), "l"(c)); return r;
}
__device__ __forceinline__ ull f2_add(ull a, ull b) {
    ull r; asm("add.rn.f32x2 %0,%1,%2;" : "=l"(r) : "l"(a), "l"(b)); return r;
}
__device__ __forceinline__ ull f2_pack(float lo, float hi) {
    ull r; asm("mov.b64 %0,{%1,%2};" : "=l"(r) : "f"(lo), "f"(hi)); return r;
}
__device__ __forceinline__ float2 f2_unpack(ull v) {
    float lo, hi; asm("mov.b64 {%0,%1},%2;" : "=f"(lo), "=f"(hi) : "l"(v));
    return make_float2(lo, hi);
}

static constexpr int   NC     = 16;
static constexpr int   NCELLS = NC * NC * NC;
static constexpr float ORG    = -4.0f;
static constexpr float INV_CS = 2.0f;
static constexpr int   MAXVP  = 6896;             // mult of 16
static constexpr int   NPAIRS = MAXVP / 2;        // 3448
static constexpr int   NGRP   = MAXVP / 8;        // 862
static constexpr int   NSUPP  = 108;              // supers (108*8 >= 862)
static constexpr int   NSP    = NSUPP / 2;        // 54 super-pairs
static constexpr int   NGPP   = NSUPP * 4;        // 432 group-pairs (padded)
static constexpr int   SCAP   = 24;               // super list cap
static constexpr int   SSTR   = SCAP + 1;         // stride incl. dummy slot
static constexpr int   GCAP   = 128;              // group list cap
static constexpr int   GSTR   = GCAP + 1;         // stride incl. dummy slot
static constexpr int   SUBN   = 216;              // pass-A pairs (every 16th)

__device__ float4 g_vs[MAXVP];
__device__ int    g_vidx[MAXVP];
__device__ float4 g_vp[MAXVP];                    // pair-packed verts
__device__ unsigned short g_vidx16[MAXVP];
__device__ float4 g_gpA[NGPP], g_gpB[NGPP];       // group-pair bounds (padded)
__device__ float4 g_spA[NSP], g_spB[NSP];         // super-pair bounds

__device__ __forceinline__ int cell_coord(float x) {
    int c = (int)floorf((x - ORG) * INV_CS);
    return min(NC - 1, max(0, c));
}
__device__ __forceinline__ int spread4(int v) {
    return (v & 1) | ((v & 2) << 2) | ((v & 4) << 4) | ((v & 8) << 6);
}
__device__ __forceinline__ int morton_cell(float x, float y, float z) {
    return spread4(cell_coord(x)) | (spread4(cell_coord(y)) << 1)
         | (spread4(cell_coord(z)) << 2);
}

// ─────────── single-CTA build ───────────
__global__ void __launch_bounds__(1024) build_kernel(const float* __restrict__ verts,
                                                     int nv)
{
    __shared__ int    scnt[NCELLS];
    __shared__ int    part[1024];
    __shared__ float4 sgb[NGRP];
    __shared__ float4 ssb[NSUPP];
    const int tid = threadIdx.x;

    for (int i = tid; i < NCELLS; i += 1024) scnt[i] = 0;
    __syncthreads();

    float lx[7], ly[7], lz[7];
    int   lc[7], lr[7];
    int cnt = 0;
    for (int j = tid; j < nv; j += 1024) {
        float x = verts[3 * j], y = verts[3 * j + 1], z = verts[3 * j + 2];
        int cid = morton_cell(x, y, z);
        lx[cnt] = x; ly[cnt] = y; lz[cnt] = z;
        lc[cnt] = cid;
        lr[cnt] = atomicAdd(&scnt[cid], 1);
        ++cnt;
    }
    __syncthreads();

    int base = tid * 4;
    int c0 = scnt[base], c1 = scnt[base + 1], c2 = scnt[base + 2], c3 = scnt[base + 3];
    int s = c0 + c1 + c2 + c3;
    part[tid] = s;
    __syncthreads();
    for (int off = 1; off < 1024; off <<= 1) {
        int v = (tid >= off) ? part[tid - off] : 0;
        __syncthreads(); part[tid] += v; __syncthreads();
    }
    int excl = part[tid] - s;
    scnt[base]     = excl;
    scnt[base + 1] = excl + c0;
    scnt[base + 2] = excl + c0 + c1;
    scnt[base + 3] = excl + c0 + c1 + c2;
    __syncthreads();

    for (int u = 0; u < cnt; ++u) {
        int pos = scnt[lc[u]] + lr[u];
        float x = lx[u], y = ly[u], z = lz[u];
        float sv = __fadd_rn(__fadd_rn(__fmul_rn(x, x), __fmul_rn(y, y)),
                             __fmul_rn(z, z));
        g_vs[pos]   = make_float4(x, y, z, sv);
        g_vidx[pos] = tid + 1024 * u;
    }
    for (int j = nv + tid; j < MAXVP; j += 1024) {
        g_vs[j]   = make_float4(1e7f, 1e7f, 1e7f, CUDART_INF_F);
        g_vidx[j] = 0xFFFF;
    }
    __syncthreads();

    // group spheres
    for (int g = tid; g < NGRP; g += 1024) {
        float mnx = FLT_MAX, mny = FLT_MAX, mnz = FLT_MAX;
        float mxx = -FLT_MAX, mxy = -FLT_MAX, mxz = -FLT_MAX;
        bool any = false;
        #pragma unroll
        for (int k = 0; k < 8; ++k) {
            float4 v = g_vs[g * 8 + k];
            if (isinf(v.w)) continue;
            any = true;
            mnx = fminf(mnx, v.x); mxx = fmaxf(mxx, v.x);
            mny = fminf(mny, v.y); mxy = fmaxf(mxy, v.y);
            mnz = fminf(mnz, v.z); mxz = fmaxf(mxz, v.z);
        }
        float4 b;
        if (!any) {
            b = make_float4(1e7f, 1e7f, 1e7f, 0.f);
        } else {
            float cx = 0.5f * (mnx + mxx), cy = 0.5f * (mny + mxy), cz = 0.5f * (mnz + mxz);
            float m2 = 0.f;
            #pragma unroll
            for (int k = 0; k < 8; ++k) {
                float4 v = g_vs[g * 8 + k];
                if (isinf(v.w)) continue;
                float dx = v.x - cx, dy = v.y - cy, dz = v.z - cz;
                m2 = fmaxf(m2, dx * dx + dy * dy + dz * dz);
            }
            b = make_float4(cx, cy, cz, sqrtf(m2) * 1.0002f + 1e-5f);
        }
        sgb[g] = b;
    }
    __syncthreads();

    // super spheres
    if (tid < NSUPP) {
        float mnx = FLT_MAX, mny = FLT_MAX, mnz = FLT_MAX;
        float mxx = -FLT_MAX, mxy = -FLT_MAX, mxz = -FLT_MAX;
        bool any = false;
        for (int k = 0; k < 8; ++k) {
            int g = tid * 8 + k;
            if (g >= NGRP) break;
            float4 b = sgb[g];
            if (b.x > 9e6f) continue;
            any = true;
            mnx = fminf(mnx, b.x - b.w); mxx = fmaxf(mxx, b.x + b.w);
            mny = fminf(mny, b.y - b.w); mxy = fmaxf(mxy, b.y + b.w);
            mnz = fminf(mnz, b.z - b.w); mxz = fmaxf(mxz, b.z + b.w);
        }
        if (!any) {
            ssb[tid] = make_float4(1e7f, 1e7f, 1e7f, 0.f);
        } else {
            float cx = 0.5f * (mnx + mxx), cy = 0.5f * (mny + mxy), cz = 0.5f * (mnz + mxz);
            float mr = 0.f;
            for (int k = 0; k < 8; ++k) {
                int g = tid * 8 + k;
                if (g >= NGRP) break;
                float4 b = sgb[g];
                if (b.x > 9e6f) continue;
                float dx = b.x - cx, dy = b.y - cy, dz = b.z - cz;
                mr = fmaxf(mr, sqrtf(dx * dx + dy * dy + dz * dz) + b.w);
            }
            ssb[tid] = make_float4(cx, cy, cz, mr * 1.0002f + 1e-5f);
        }
    }
    __syncthreads();

    // pack: verts pairwise, idx16, group-pair (padded to NGPP) & super-pair bounds
    for (int p = tid; p < NPAIRS; p += 1024) {
        float4 v0 = g_vs[2 * p], v1 = g_vs[2 * p + 1];
        g_vp[2 * p]     = make_float4(v0.x, v1.x, v0.y, v1.y);
        g_vp[2 * p + 1] = make_float4(v0.z, v1.z, v0.w, v1.w);
        g_vidx16[2 * p]     = (unsigned short)g_vidx[2 * p];
        g_vidx16[2 * p + 1] = (unsigned short)g_vidx[2 * p + 1];
    }
    for (int gp = tid; gp < NGPP; gp += 1024) {
        int g0 = 2 * gp, g1 = 2 * gp + 1;
        float4 b0 = (g0 < NGRP) ? sgb[g0] : make_float4(1e7f, 1e7f, 1e7f, 0.f);
        float4 b1 = (g1 < NGRP) ? sgb[g1] : make_float4(1e7f, 1e7f, 1e7f, 0.f);
        g_gpA[gp] = make_float4(b0.x, b1.x, b0.y, b1.y);
        g_gpB[gp] = make_float4(b0.z, b1.z, b0.w, b1.w);
    }
    if (tid < NSP) {
        float4 b0 = ssb[2 * tid], b1 = ssb[2 * tid + 1];
        g_spA[tid] = make_float4(b0.x, b1.x, b0.y, b1.y);
        g_spB[tid] = make_float4(b0.z, b1.z, b0.w, b1.w);
    }
}

// ─────────── NN + skinning ───────────
static constexpr int SVP_OFF   = 0;                        // float4[MAXVP]
static constexpr int SGPA_OFF  = MAXVP * 16;               // float4[NGPP]
static constexpr int SGPB_OFF  = SGPA_OFF + NGPP * 16;
static constexpr int SSPA_OFF  = SGPB_OFF + NGPP * 16;     // float4[NSP]
static constexpr int SSPB_OFF  = SSPA_OFF + NSP * 16;
static constexpr int SVIDX_OFF = SSPB_OFF + NSP * 16;      // u16[MAXVP]
static constexpr int SBONE_OFF = SVIDX_OFF + MAXVP * 2;    // float[384]
static constexpr int SSUPL_OFF = SBONE_OFF + 1536;         // u8 [256*SSTR]
static constexpr int SGRPL_OFF = SSUPL_OFF + 256 * SSTR;   // u16[256*GSTR]
static constexpr int SMEM_TOT  = SGRPL_OFF + 256 * GSTR * 2;   // ~213.7 KB

__global__ void __launch_bounds__(256, 1) nn_kernel(
    const float* __restrict__ xyz,
    const float* __restrict__ rot,
    const float* __restrict__ W,
    const float* __restrict__ bones,
    float* __restrict__ out,
    int n, int nv)
{
    extern __shared__ char smem[];
    ulonglong2* sVP  = reinterpret_cast<ulonglong2*>(smem + SVP_OFF);
    ulonglong2* sGPA = reinterpret_cast<ulonglong2*>(smem + SGPA_OFF);
    ulonglong2* sGPB = reinterpret_cast<ulonglong2*>(smem + SGPB_OFF);
    ulonglong2* sSPA = reinterpret_cast<ulonglong2*>(smem + SSPA_OFF);
    ulonglong2* sSPB = reinterpret_cast<ulonglong2*>(smem + SSPB_OFF);
    unsigned int*   sVidx = reinterpret_cast<unsigned int*>(smem + SVIDX_OFF);
    float*          sB    = reinterpret_cast<float*>(smem + SBONE_OFF);
    unsigned char*  supL  = reinterpret_cast<unsigned char*>(smem + SSUPL_OFF);
    unsigned short* grpL  = reinterpret_cast<unsigned short*>(smem + SGRPL_OFF);

    const int tid = threadIdx.x;
    {   // cooperative smem fill
        float4* d = reinterpret_cast<float4*>(smem + SVP_OFF);
        for (int j = tid; j < MAXVP; j += 256) d[j] = g_vp[j];
        float4* ga = reinterpret_cast<float4*>(smem + SGPA_OFF);
        float4* gb = reinterpret_cast<float4*>(smem + SGPB_OFF);
        for (int j = tid; j < NGPP; j += 256) { ga[j] = g_gpA[j]; gb[j] = g_gpB[j]; }
        float4* sa = reinterpret_cast<float4*>(smem + SSPA_OFF);
        float4* sbp = reinterpret_cast<float4*>(smem + SSPB_OFF);
        if (tid < NSP) { sa[tid] = g_spA[tid]; sbp[tid] = g_spB[tid]; }
        unsigned int* vi = reinterpret_cast<unsigned int*>(smem + SVIDX_OFF);
        const unsigned int* gvi = reinterpret_cast<const unsigned int*>(g_vidx16);
        for (int j = tid; j < MAXVP / 2; j += 256) vi[j] = gvi[j];
        for (int j = tid; j < 24 * 16; j += 256) sB[j] = bones[j];
    }
    __syncthreads();

    const int i = blockIdx.x * 256 + tid;
    const bool valid = (i < n);
    const int pt = valid ? i : (n - 1);

    const float px = xyz[3 * pt + 0];
    const float py = xyz[3 * pt + 1];
    const float pz = xyz[3 * pt + 2];
    const float sx = __fadd_rn(__fadd_rn(__fmul_rn(px, px), __fmul_rn(py, py)),
                               __fmul_rn(pz, pz));

    const ull Px2 = f2_pack(px, px), Py2 = f2_pack(py, py), Pz2 = f2_pack(pz, pz);
    const ull NPx2 = f2_pack(-px, -px), NPy2 = f2_pack(-py, -py), NPz2 = f2_pack(-pz, -pz);
    const ull Sx2 = f2_pack(sx, sx), M2 = f2_pack(-2.0f, -2.0f);

    // ── Pass A: subsample -> ub2 (exact formula on real verts)
    float m0 = CUDART_INF_F, m1 = CUDART_INF_F;
    for (int k = 0; k < SUBN; ++k) {
        int p = k * 16;
        ulonglong2 ab = sVP[2 * p], cd = sVP[2 * p + 1];
        ull dot = f2_mul(Px2, ab.x);
        dot = f2_fma(Py2, ab.y, dot);
        dot = f2_fma(Pz2, cd.x, dot);
        float2 d = f2_unpack(f2_add(f2_fma(M2, dot, Sx2), cd.y));
        m0 = fminf(m0, d.x);
        m1 = fminf(m1, d.y);
    }
    const float ub2 = fminf(m0, m1);

    const float rs2 = (ub2 + 1e-3f) * 1.001f;
    const float rs  = sqrtf(rs2);
    const ull Rs2p  = f2_pack(rs2, rs2);
    const ull TwoRs = f2_pack(2.0f * rs, 2.0f * rs);

    // ── Pass B1: super-pairs; dummy-slot compaction (fail -> slot SCAP)
    unsigned char* myS = supL + tid * SSTR;
    int sc = 0;
    for (int sp = 0; sp < NSP; ++sp) {
        ulonglong2 A = sSPA[sp], B = sSPB[sp];
        ull dx = f2_add(A.x, NPx2);
        ull dy = f2_add(A.y, NPy2);
        ull dz = f2_add(B.x, NPz2);
        ull d2 = f2_mul(dx, dx);
        d2 = f2_fma(dy, dy, d2);
        d2 = f2_fma(dz, dz, d2);
        ull thr = f2_fma(B.y, B.y, Rs2p);
        thr = f2_fma(TwoRs, B.y, thr);
        float2 dd = f2_unpack(d2), tt = f2_unpack(thr);
        bool p0 = dd.x <= tt.x, p1 = dd.y <= tt.y;
        myS[p0 ? min(sc, SCAP - 1) : SCAP] = (unsigned char)(2 * sp);     sc += p0;
        myS[p1 ? min(sc, SCAP - 1) : SCAP] = (unsigned char)(2 * sp + 1); sc += p1;
    }
    const bool sofl = (sc > SCAP);

    // ── Pass B2: groups of passing supers (dummy-slot compaction)
    unsigned short* myG = grpL + tid * GSTR;
    int gc = 0;
    const int nIt = sofl ? NSUPP : sc;
    for (int t = 0; t < nIt; ++t) {
        int sid = sofl ? t : (int)myS[t];
        #pragma unroll
        for (int q = 0; q < 4; ++q) {
            int gp = sid * 4 + q;          // < 432 = NGPP (padded, safe)
            ulonglong2 A = sGPA[gp], B = sGPB[gp];
            ull dx = f2_add(A.x, NPx2);
            ull dy = f2_add(A.y, NPy2);
            ull dz = f2_add(B.x, NPz2);
            ull d2 = f2_mul(dx, dx);
            d2 = f2_fma(dy, dy, d2);
            d2 = f2_fma(dz, dz, d2);
            ull thr = f2_fma(B.y, B.y, Rs2p);
            thr = f2_fma(TwoRs, B.y, thr);
            float2 dd = f2_unpack(d2), tt = f2_unpack(thr);
            bool p0 = dd.x <= tt.x, p1 = dd.y <= tt.y;
            myG[p0 ? min(gc, GCAP - 1) : GCAP] = (unsigned short)(2 * gp);     gc += p0;
            myG[p1 ? min(gc, GCAP - 1) : GCAP] = (unsigned short)(2 * gp + 1); gc += p1;
        }
    }
    const bool gofl = (gc > GCAP);

    // ── Pass C: exact eval of candidate groups (bit-exact reference d2)
    float bl = CUDART_INF_F;
    int   bi = 0x7FFFFFFF;
    const int nE = gofl ? NGRP : gc;
    for (int t = 0; t < nE; ++t) {
        int g = gofl ? t : (int)myG[t];
        if (g >= NGRP) continue;           // padding group ids (never real)
        #pragma unroll
        for (int q = 0; q < 4; ++q) {
            int p = g * 4 + q;
            ulonglong2 ab = sVP[2 * p], cd = sVP[2 * p + 1];
            ull dot = f2_mul(Px2, ab.x);
            dot = f2_fma(Py2, ab.y, dot);
            dot = f2_fma(Pz2, cd.x, dot);
            float2 d = f2_unpack(f2_add(f2_fma(M2, dot, Sx2), cd.y));
            unsigned int ip = sVidx[p];
            int i0 = (int)(ip & 0xFFFFu), i1 = (int)(ip >> 16);
            bool b0 = (d.x < bl) || (d.x == bl && i0 < bi);
            bl = b0 ? d.x : bl;  bi = b0 ? i0 : bi;
            bool b1 = (d.y < bl) || (d.y == bl && i1 < bi);
            bl = b1 ? d.y : bl;  bi = b1 ? i1 : bi;
        }
    }
    const int bidx = min(bi, nv - 1);      // defensive clamp

    if (!valid) return;

    // ── skinning epilogue ──
    float T[16];
    #pragma unroll
    for (int k = 0; k < 16; ++k) T[k] = 0.0f;
    const float* wrow = W + (size_t)bidx * 24;
    #pragma unroll
    for (int j = 0; j < 24; ++j) {
        float wj = __ldg(wrow + j);
        #pragma unroll
        for (int k = 0; k < 16; ++k) T[k] = fmaf(wj, sB[j * 16 + k], T[k]);
    }

    #pragma unroll
    for (int ii = 0; ii < 3; ++ii) {
        float v = T[4 * ii + 3];
        v = fmaf(T[4 * ii + 0], px, v);
        v = fmaf(T[4 * ii + 1], py, v);
        v = fmaf(T[4 * ii + 2], pz, v);
        out[3 * pt + ii] = v;
    }

    const float4 q = *reinterpret_cast<const float4*>(rot + 4 * pt);
    float qn = rsqrtf(q.x * q.x + q.y * q.y + q.z * q.z + q.w * q.w);
    float qr = q.x * qn, qx = q.y * qn, qy = q.z * qn, qz = q.w * qn;

    float R[3][3];
    R[0][0] = 1.0f - 2.0f * (qy * qy + qz * qz);
    R[0][1] = 2.0f * (qx * qy - qr * qz);
    R[0][2] = 2.0f * (qx * qz + qr * qy);
    R[1][0] = 2.0f * (qx * qy + qr * qz);
    R[1][1] = 1.0f - 2.0f * (qx * qx + qz * qz);
    R[1][2] = 2.0f * (qy * qz - qr * qx);
    R[2][0] = 2.0f * (qx * qz - qr * qy);
    R[2][1] = 2.0f * (qy * qz + qr * qx);
    R[2][2] = 1.0f - 2.0f * (qx * qx + qy * qy);

    float* out_R = out + (size_t)3 * n;
    #pragma unroll
    for (int ii = 0; ii < 3; ++ii) {
        #pragma unroll
        for (int k = 0; k < 3; ++k) {
            float v = T[4 * ii + 0] * R[0][k];
            v = fmaf(T[4 * ii + 1], R[1][k], v);
            v = fmaf(T[4 * ii + 2], R[2][k], v);
            out_R[9 * pt + 3 * ii + k] = v;
        }
    }

    float4* out_T = reinterpret_cast<float4*>(out + (size_t)12 * n) + (size_t)4 * pt;
    #pragma unroll
    for (int k = 0; k < 4; ++k)
        out_T[k] = make_float4(T[4 * k + 0], T[4 * k + 1], T[4 * k + 2], T[4 * k + 3]);
}

extern "C" void kernel_launch(void* const* d_in, const int* in_sizes, int n_in,
                              void* d_out, int out_size)
{
    const float* xyz   = (const float*)d_in[0];
    const float* rot   = (const float*)d_in[1];
    const float* verts = (const float*)d_in[2];
    const float* W     = (const float*)d_in[3];
    const float* bones = (const float*)d_in[4];
    float* out = (float*)d_out;

    const int n  = in_sizes[0] / 3;   // 100000
    const int nv = in_sizes[2] / 3;   // 6890

    cudaFuncSetAttribute(nn_kernel,
                         cudaFuncAttributeMaxDynamicSharedMemorySize, SMEM_TOT);

    build_kernel<<<1, 1024>>>(verts, nv);
    nn_kernel<<<(n + 255) / 256, 256, SMEM_TOT>>>(xyz, rot, W, bones, out, n, nv);
}

// round 14
// speedup vs baseline: 3.2512x; 1.4187x over previous
#include <cuda_runtime.h>
#include <math_constants.h>
#include <float.h>

// SMPL NN skinning — Morton-sorted verts AND points, per-thread pruned exact
// search with cell-based seed. Sorted points make warp lanes' candidate lists
// coherent (broadcast smem/global reads, warp-max ~= mean trip counts).
//  seed: evaluate 3 groups at vstart[cell(p)]>>3 (exact d2) -> ub2
//  B1/B2: packed-f32x2 sphere tests, dummy-slot branch-free compaction
//  C: exact bit-identical reference d2 on candidate groups, lex (d2,idx) min
// Output: [0,3n) x_bar | [3n,12n) rotation_bar | [12n,28n) T_fwd

typedef unsigned long long ull;

__device__ __forceinline__ ull f2_mul(ull a, ull b) {
    ull r; asm("mul.rn.f32x2 %0,%1,%2;" : "=l"(r) : "l"(a), "l"(b)); return r;
}
__device__ __forceinline__ ull f2_fma(ull a, ull b, ull c) {
    ull r; asm("fma.rn.f32x2 %0,%1,%2,%3;" : "=l"(r) : "l"(a), "l"(b), "l"(c)); return r;
}
__device__ __forceinline__ ull f2_add(ull a, ull b) {
    ull r; asm("add.rn.f32x2 %0,%1,%2;" : "=l"(r) : "l"(a), "l"(b)); return r;
}
__device__ __forceinline__ ull f2_pack(float lo, float hi) {
    ull r; asm("mov.b64 %0,{%1,%2};" : "=l"(r) : "f"(lo), "f"(hi)); return r;
}
__device__ __forceinline__ float2 f2_unpack(ull v) {
    float lo, hi; asm("mov.b64 {%0,%1},%2;" : "=f"(lo), "=f"(hi) : "l"(v));
    return make_float2(lo, hi);
}

static constexpr int   NC     = 16;
static constexpr int   NCELLS = NC * NC * NC;     // 4096
static constexpr float ORG    = -4.0f;
static constexpr float INV_CS = 2.0f;
static constexpr int   MAXN   = 100000;
static constexpr int   MAXVP  = 6896;             // mult of 16
static constexpr int   NPAIRS = MAXVP / 2;
static constexpr int   NGRP   = MAXVP / 8;        // 862
static constexpr int   NSUPP  = 108;
static constexpr int   NSP    = NSUPP / 2;        // 54
static constexpr int   NGPP   = NSUPP * 4;        // 432 group-pairs (padded)
static constexpr int   SCAP   = 16;
static constexpr int   GCAP   = 96;

// vert side
__device__ int    g_vcount[NCELLS];
__device__ int    g_vstart[NCELLS + 1];
__device__ int    g_vrank[MAXVP];
__device__ int    g_vcellid[MAXVP];
__device__ float4 g_vs[MAXVP];
__device__ int    g_vidx[MAXVP];
__device__ float4 g_vp[MAXVP];                    // pair-packed verts
__device__ unsigned short g_vidx16[MAXVP];
__device__ float4 g_gpA[NGPP], g_gpB[NGPP];
__device__ float4 g_spA[NSP], g_spB[NSP];
// point side
__device__ int    g_pcount[NCELLS];
__device__ int    g_pstart[NCELLS + 1];
__device__ int    g_prank[MAXN];
__device__ int    g_pcellid[MAXN];
__device__ int    g_order[MAXN];

__device__ __forceinline__ int cell_coord(float x) {
    int c = (int)floorf((x - ORG) * INV_CS);
    return min(NC - 1, max(0, c));
}
__device__ __forceinline__ int spread4(int v) {
    return (v & 1) | ((v & 2) << 2) | ((v & 4) << 4) | ((v & 8) << 6);
}
__device__ __forceinline__ int morton_cell(float x, float y, float z) {
    return spread4(cell_coord(x)) | (spread4(cell_coord(y)) << 1)
         | (spread4(cell_coord(z)) << 2);
}

// ───────────── build kernels ─────────────
__global__ void zero_counts(int nv) {
    int i = blockIdx.x * blockDim.x + threadIdx.x;   // 4096 threads
    if (i < NCELLS) { g_vcount[i] = 0; g_pcount[i] = 0; }
    for (int k = nv + i; k < MAXVP; k += NCELLS) {
        g_vs[k]   = make_float4(1e7f, 1e7f, 1e7f, CUDART_INF_F);
        g_vidx[k] = 0xFFFF;
    }
}

__global__ void count_kernel(const float* __restrict__ verts,
                             const float* __restrict__ xyz, int nv, int n) {
    int i = blockIdx.x * blockDim.x + threadIdx.x;
    if (i < nv) {
        int cid = morton_cell(verts[3 * i], verts[3 * i + 1], verts[3 * i + 2]);
        g_vcellid[i] = cid;
        g_vrank[i] = atomicAdd(&g_vcount[cid], 1);
    }
    if (i < n) {
        int cid = morton_cell(xyz[3 * i], xyz[3 * i + 1], xyz[3 * i + 2]);
        g_pcellid[i] = cid;
        g_prank[i] = atomicAdd(&g_pcount[cid], 1);
    }
}

__global__ void __launch_bounds__(1024) scan_offsets() {
    __shared__ int part[1024];
    const int t = threadIdx.x;
    int* cnt = blockIdx.x ? g_pcount : g_vcount;
    int* st  = blockIdx.x ? g_pstart : g_vstart;
    const int CHUNK = NCELLS / 1024;   // 4
    int base = t * CHUNK, s = 0;
    #pragma unroll
    for (int k = 0; k < CHUNK; ++k) s += cnt[base + k];
    part[t] = s;
    __syncthreads();
    for (int off = 1; off < 1024; off <<= 1) {
        int v = (t >= off) ? part[t - off] : 0;
        __syncthreads(); part[t] += v; __syncthreads();
    }
    int excl = part[t] - s;
    #pragma unroll
    for (int k = 0; k < CHUNK; ++k) { st[base + k] = excl; excl += cnt[base + k]; }
    if (t == 1023) st[NCELLS] = part[1023];
}

__global__ void scatter_kernel(const float* __restrict__ verts, int nv, int n) {
    int i = blockIdx.x * blockDim.x + threadIdx.x;
    if (i < nv) {
        float x = verts[3 * i], y = verts[3 * i + 1], z = verts[3 * i + 2];
        float sv = __fadd_rn(__fadd_rn(__fmul_rn(x, x), __fmul_rn(y, y)),
                             __fmul_rn(z, z));
        int pos = g_vstart[g_vcellid[i]] + g_vrank[i];
        g_vs[pos]   = make_float4(x, y, z, sv);
        g_vidx[pos] = i;
    }
    if (i < n) g_order[g_pstart[g_pcellid[i]] + g_prank[i]] = i;
}

__global__ void __launch_bounds__(1024) bounds_kernel(int nv) {
    __shared__ float4 sgb[NGRP];
    __shared__ float4 ssb[NSUPP];
    const int tid = threadIdx.x;

    for (int g = tid; g < NGRP; g += 1024) {
        float mnx = FLT_MAX, mny = FLT_MAX, mnz = FLT_MAX;
        float mxx = -FLT_MAX, mxy = -FLT_MAX, mxz = -FLT_MAX;
        bool any = false;
        #pragma unroll
        for (int k = 0; k < 8; ++k) {
            float4 v = g_vs[g * 8 + k];
            if (isinf(v.w)) continue;
            any = true;
            mnx = fminf(mnx, v.x); mxx = fmaxf(mxx, v.x);
            mny = fminf(mny, v.y); mxy = fmaxf(mxy, v.y);
            mnz = fminf(mnz, v.z); mxz = fmaxf(mxz, v.z);
        }
        float4 b;
        if (!any) {
            b = make_float4(1e7f, 1e7f, 1e7f, 0.f);
        } else {
            float cx = 0.5f * (mnx + mxx), cy = 0.5f * (mny + mxy), cz = 0.5f * (mnz + mxz);
            float m2 = 0.f;
            #pragma unroll
            for (int k = 0; k < 8; ++k) {
                float4 v = g_vs[g * 8 + k];
                if (isinf(v.w)) continue;
                float dx = v.x - cx, dy = v.y - cy, dz = v.z - cz;
                m2 = fmaxf(m2, dx * dx + dy * dy + dz * dz);
            }
            b = make_float4(cx, cy, cz, sqrtf(m2) * 1.0002f + 1e-5f);
        }
        sgb[g] = b;
    }
    __syncthreads();

    if (tid < NSUPP) {
        float mnx = FLT_MAX, mny = FLT_MAX, mnz = FLT_MAX;
        float mxx = -FLT_MAX, mxy = -FLT_MAX, mxz = -FLT_MAX;
        bool any = false;
        for (int k = 0; k < 8; ++k) {
            int g = tid * 8 + k;
            if (g >= NGRP) break;
            float4 b = sgb[g];
            if (b.x > 9e6f) continue;
            any = true;
            mnx = fminf(mnx, b.x - b.w); mxx = fmaxf(mxx, b.x + b.w);
            mny = fminf(mny, b.y - b.w); mxy = fmaxf(mxy, b.y + b.w);
            mnz = fminf(mnz, b.z - b.w); mxz = fmaxf(mxz, b.z + b.w);
        }
        if (!any) {
            ssb[tid] = make_float4(1e7f, 1e7f, 1e7f, 0.f);
        } else {
            float cx = 0.5f * (mnx + mxx), cy = 0.5f * (mny + mxy), cz = 0.5f * (mnz + mxz);
            float mr = 0.f;
            for (int k = 0; k < 8; ++k) {
                int g = tid * 8 + k;
                if (g >= NGRP) break;
                float4 b = sgb[g];
                if (b.x > 9e6f) continue;
                float dx = b.x - cx, dy = b.y - cy, dz = b.z - cz;
                mr = fmaxf(mr, sqrtf(dx * dx + dy * dy + dz * dz) + b.w);
            }
            ssb[tid] = make_float4(cx, cy, cz, mr * 1.0002f + 1e-5f);
        }
    }
    __syncthreads();

    for (int p = tid; p < NPAIRS; p += 1024) {
        float4 v0 = g_vs[2 * p], v1 = g_vs[2 * p + 1];
        g_vp[2 * p]     = make_float4(v0.x, v1.x, v0.y, v1.y);
        g_vp[2 * p + 1] = make_float4(v0.z, v1.z, v0.w, v1.w);
        g_vidx16[2 * p]     = (unsigned short)g_vidx[2 * p];
        g_vidx16[2 * p + 1] = (unsigned short)g_vidx[2 * p + 1];
    }
    for (int gp = tid; gp < NGPP; gp += 1024) {
        int g0 = 2 * gp, g1 = 2 * gp + 1;
        float4 b0 = (g0 < NGRP) ? sgb[g0] : make_float4(1e7f, 1e7f, 1e7f, 0.f);
        float4 b1 = (g1 < NGRP) ? sgb[g1] : make_float4(1e7f, 1e7f, 1e7f, 0.f);
        g_gpA[gp] = make_float4(b0.x, b1.x, b0.y, b1.y);
        g_gpB[gp] = make_float4(b0.z, b1.z, b0.w, b1.w);
    }
    if (tid < NSP) {
        float4 b0 = ssb[2 * tid], b1 = ssb[2 * tid + 1];
        g_spA[tid] = make_float4(b0.x, b1.x, b0.y, b1.y);
        g_spB[tid] = make_float4(b0.z, b1.z, b0.w, b1.w);
    }
}

// ─────────── NN + skinning ───────────
// smem (bytes): gpA/gpB 13824 | spA/spB 1728 | bones 1536 |
//               supL u8[(SCAP+1)*256] 4352 | grpL u16[(GCAP+1)*256] 49664
static constexpr int SGPA_OFF  = 0;
static constexpr int SGPB_OFF  = SGPA_OFF + NGPP * 16;
static constexpr int SSPA_OFF  = SGPB_OFF + NGPP * 16;
static constexpr int SSPB_OFF  = SSPA_OFF + NSP * 16;
static constexpr int SBONE_OFF = SSPB_OFF + NSP * 16;
static constexpr int SSUPL_OFF = SBONE_OFF + 1536;
static constexpr int SGRPL_OFF = SSUPL_OFF + (SCAP + 1) * 256;
static constexpr int SMEM_TOT  = SGRPL_OFF + (GCAP + 1) * 256 * 2;   // 71104

__global__ void __launch_bounds__(256, 2) nn_kernel(
    const float* __restrict__ xyz,
    const float* __restrict__ rot,
    const float* __restrict__ W,
    const float* __restrict__ bones,
    float* __restrict__ out,
    int n, int nv)
{
    extern __shared__ char smem[];
    ulonglong2* sGPA = reinterpret_cast<ulonglong2*>(smem + SGPA_OFF);
    ulonglong2* sGPB = reinterpret_cast<ulonglong2*>(smem + SGPB_OFF);
    ulonglong2* sSPA = reinterpret_cast<ulonglong2*>(smem + SSPA_OFF);
    ulonglong2* sSPB = reinterpret_cast<ulonglong2*>(smem + SSPB_OFF);
    float*          sB   = reinterpret_cast<float*>(smem + SBONE_OFF);
    unsigned char*  supL = reinterpret_cast<unsigned char*>(smem + SSUPL_OFF);
    unsigned short* grpL = reinterpret_cast<unsigned short*>(smem + SGRPL_OFF);

    const int tid = threadIdx.x;
    {
        float4* ga = reinterpret_cast<float4*>(smem + SGPA_OFF);
        float4* gb = reinterpret_cast<float4*>(smem + SGPB_OFF);
        for (int j = tid; j < NGPP; j += 256) { ga[j] = g_gpA[j]; gb[j] = g_gpB[j]; }
        float4* sa = reinterpret_cast<float4*>(smem + SSPA_OFF);
        float4* sbp = reinterpret_cast<float4*>(smem + SSPB_OFF);
        if (tid < NSP) { sa[tid] = g_spA[tid]; sbp[tid] = g_spB[tid]; }
        for (int j = tid; j < 24 * 16; j += 256) sB[j] = bones[j];
    }
    __syncthreads();

    const int i = blockIdx.x * 256 + tid;
    const bool valid = (i < n);
    const int pid = g_order[valid ? i : (n - 1)];

    const float px = xyz[3 * pid + 0];
    const float py = xyz[3 * pid + 1];
    const float pz = xyz[3 * pid + 2];
    const float sx = __fadd_rn(__fadd_rn(__fmul_rn(px, px), __fmul_rn(py, py)),
                               __fmul_rn(pz, pz));

    const ull Px2 = f2_pack(px, px), Py2 = f2_pack(py, py), Pz2 = f2_pack(pz, pz);
    const ull NPx2 = f2_pack(-px, -px), NPy2 = f2_pack(-py, -py), NPz2 = f2_pack(-pz, -pz);
    const ull Sx2 = f2_pack(sx, sx), M2 = f2_pack(-2.0f, -2.0f);

    const ulonglong2* vp = reinterpret_cast<const ulonglong2*>(g_vp);
    const unsigned int* vix = reinterpret_cast<const unsigned int*>(g_vidx16);

    float bl = CUDART_INF_F;
    int   bi = 0x7FFFFFFF;

    auto evalg = [&](int g) {
        #pragma unroll
        for (int q = 0; q < 4; ++q) {
            int p = g * 4 + q;
            ulonglong2 ab = vp[2 * p], cd = vp[2 * p + 1];
            ull dot = f2_mul(Px2, ab.x);
            dot = f2_fma(Py2, ab.y, dot);
            dot = f2_fma(Pz2, cd.x, dot);
            float2 d = f2_unpack(f2_add(f2_fma(M2, dot, Sx2), cd.y));
            unsigned int ip = vix[p];
            int i0 = (int)(ip & 0xFFFFu), i1 = (int)(ip >> 16);
            bool b0 = (d.x < bl) || (d.x == bl && i0 < bi);
            bl = b0 ? d.x : bl;  bi = b0 ? i0 : bi;
            bool b1 = (d.y < bl) || (d.y == bl && i1 < bi);
            bl = b1 ? d.y : bl;  bi = b1 ? i1 : bi;
        }
    };

    // ── seed: groups around this point's Morton cell (exact eval)
    {
        int cid = morton_cell(px, py, pz);
        int vpos = g_vstart[cid];
        int gs = min(max(vpos >> 3, 0), NGRP - 1);
        evalg(max(gs - 1, 0));
        evalg(gs);
        evalg(min(gs + 1, NGRP - 1));
    }

    const float rs2 = (bl + 1e-3f) * 1.001f;
    const float rs  = sqrtf(rs2);
    const ull Rs2p  = f2_pack(rs2, rs2);
    const ull TwoRs = f2_pack(2.0f * rs, 2.0f * rs);

    // ── B1: super-pairs; dummy-slot compaction (lane-interleaved lists)
    int sc = 0;
    for (int sp = 0; sp < NSP; ++sp) {
        ulonglong2 A = sSPA[sp], B = sSPB[sp];
        ull dx = f2_add(A.x, NPx2);
        ull dy = f2_add(A.y, NPy2);
        ull dz = f2_add(B.x, NPz2);
        ull d2 = f2_mul(dx, dx);
        d2 = f2_fma(dy, dy, d2);
        d2 = f2_fma(dz, dz, d2);
        ull thr = f2_fma(B.y, B.y, Rs2p);
        thr = f2_fma(TwoRs, B.y, thr);
        float2 dd = f2_unpack(d2), tt = f2_unpack(thr);
        bool p0 = dd.x <= tt.x, p1 = dd.y <= tt.y;
        supL[(p0 ? min(sc, SCAP - 1) : SCAP) * 256 + tid] = (unsigned char)(2 * sp);     sc += p0;
        supL[(p1 ? min(sc, SCAP - 1) : SCAP) * 256 + tid] = (unsigned char)(2 * sp + 1); sc += p1;
    }
    const bool sofl = (sc > SCAP);

    // ── B2: groups of passing supers
    int gc = 0;
    const int nIt = sofl ? NSUPP : sc;
    for (int t = 0; t < nIt; ++t) {
        int sid = sofl ? t : (int)supL[t * 256 + tid];
        #pragma unroll
        for (int q = 0; q < 4; ++q) {
            int gp = sid * 4 + q;          // < NGPP (padded, safe)
            ulonglong2 A = sGPA[gp], B = sGPB[gp];
            ull dx = f2_add(A.x, NPx2);
            ull dy = f2_add(A.y, NPy2);
            ull dz = f2_add(B.x, NPz2);
            ull d2 = f2_mul(dx, dx);
            d2 = f2_fma(dy, dy, d2);
            d2 = f2_fma(dz, dz, d2);
            ull thr = f2_fma(B.y, B.y, Rs2p);
            thr = f2_fma(TwoRs, B.y, thr);
            float2 dd = f2_unpack(d2), tt = f2_unpack(thr);
            bool p0 = dd.x <= tt.x, p1 = dd.y <= tt.y;
            grpL[(p0 ? min(gc, GCAP - 1) : GCAP) * 256 + tid] = (unsigned short)(2 * gp);     gc += p0;
            grpL[(p1 ? min(gc, GCAP - 1) : GCAP) * 256 + tid] = (unsigned short)(2 * gp + 1); gc += p1;
        }
    }
    const bool gofl = (gc > GCAP);

    // ── C: exact eval of candidate groups
    const int nE = gofl ? NGRP : gc;
    for (int t = 0; t < nE; ++t) {
        int g = gofl ? t : (int)grpL[t * 256 + tid];
        if (g >= NGRP) continue;
        evalg(g);
    }
    const int bidx = min(bi, nv - 1);

    if (!valid) return;

    // ── skinning epilogue ──
    float T[16];
    #pragma unroll
    for (int k = 0; k < 16; ++k) T[k] = 0.0f;
    const float* wrow = W + (size_t)bidx * 24;
    #pragma unroll
    for (int j = 0; j < 24; ++j) {
        float wj = __ldg(wrow + j);
        #pragma unroll
        for (int k = 0; k < 16; ++k) T[k] = fmaf(wj, sB[j * 16 + k], T[k]);
    }

    #pragma unroll
    for (int ii = 0; ii < 3; ++ii) {
        float v = T[4 * ii + 3];
        v = fmaf(T[4 * ii + 0], px, v);
        v = fmaf(T[4 * ii + 1], py, v);
        v = fmaf(T[4 * ii + 2], pz, v);
        out[3 * pid + ii] = v;
    }

    const float4 q = *reinterpret_cast<const float4*>(rot + 4 * pid);
    float qn = rsqrtf(q.x * q.x + q.y * q.y + q.z * q.z + q.w * q.w);
    float qr = q.x * qn, qx = q.y * qn, qy = q.z * qn, qz = q.w * qn;

    float R[3][3];
    R[0][0] = 1.0f - 2.0f * (qy * qy + qz * qz);
    R[0][1] = 2.0f * (qx * qy - qr * qz);
    R[0][2] = 2.0f * (qx * qz + qr * qy);
    R[1][0] = 2.0f * (qx * qy + qr * qz);
    R[1][1] = 1.0f - 2.0f * (qx * qx + qz * qz);
    R[1][2] = 2.0f * (qy * qz - qr * qx);
    R[2][0] = 2.0f * (qx * qz - qr * qy);
    R[2][1] = 2.0f * (qy * qz + qr * qx);
    R[2][2] = 1.0f - 2.0f * (qx * qx + qy * qy);

    float* out_R = out + (size_t)3 * n;
    #pragma unroll
    for (int ii = 0; ii < 3; ++ii) {
        #pragma unroll
        for (int k = 0; k < 3; ++k) {
            float v = T[4 * ii + 0] * R[0][k];
            v = fmaf(T[4 * ii + 1], R[1][k], v);
            v = fmaf(T[4 * ii + 2], R[2][k], v);
            out_R[9 * pid + 3 * ii + k] = v;
        }
    }

    float4* out_T = reinterpret_cast<float4*>(out + (size_t)12 * n) + (size_t)4 * pid;
    #pragma unroll
    for (int k = 0; k < 4; ++k)
        out_T[k] = make_float4(T[4 * k + 0], T[4 * k + 1], T[4 * k + 2], T[4 * k + 3]);
}

extern "C" void kernel_launch(void* const* d_in, const int* in_sizes, int n_in,
                              void* d_out, int out_size)
{
    const float* xyz   = (const float*)d_in[0];
    const float* rot   = (const float*)d_in[1];
    const float* verts = (const float*)d_in[2];
    const float* W     = (const float*)d_in[3];
    const float* bones = (const float*)d_in[4];
    float* out = (float*)d_out;

    const int n  = in_sizes[0] / 3;   // 100000
    const int nv = in_sizes[2] / 3;   // 6890
    const int mx = (n > nv) ? n : nv;

    cudaFuncSetAttribute(nn_kernel,
                         cudaFuncAttributeMaxDynamicSharedMemorySize, SMEM_TOT);

    zero_counts<<<NCELLS / 256, 256>>>(nv);
    count_kernel<<<(mx + 255) / 256, 256>>>(verts, xyz, nv, n);
    scan_offsets<<<2, 1024>>>();
    scatter_kernel<<<(mx + 255) / 256, 256>>>(verts, nv, n);
    bounds_kernel<<<1, 1024>>>(nv);
    nn_kernel<<<(n + 255) / 256, 256, SMEM_TOT>>>(xyz, rot, W, bones, out, n, nv);
}